// round 1
// baseline (speedup 1.0000x reference)
#include <cuda_runtime.h>
#include <math.h>

#define BB 64
#define LL 512
#define HH 768
#define NN 50
#define OO 768
#define MTOT (BB*NN)   // 3200

// ---------------- scratch (device globals; no allocations allowed) ----------
__device__ float g_X[MTOT*HH];     // gathered + positional-encoded input
__device__ float g_Wh[MTOT*HH];    // Wh of current GAT layer
__device__ float g_H1[MTOT*HH];    // elu(gat1)
__device__ float g_Hres[MTOT*HH];  // elu(gat2) + X
__device__ float g_T[MTOT*HH];     // Hres@Wa + ba
__device__ float g_att[BB*NN*NN];  // attention matrices
__device__ float g_D[BB*HH];       // pooled dialogue vectors

// ---------------- 1) gather + sinusoidal PE --------------------------------
__global__ void gather_pe_kernel(const float* __restrict__ emb,
                                 const int* __restrict__ ids)
{
    int bn = blockIdx.x;            // 0..3199
    int b = bn / NN, n = bn % NN;
    int h = threadIdx.x * 4;        // 192 threads * 4 = 768
    int id = ids[bn];
    float4 e = *(const float4*)(emb + ((size_t)b * LL + id) * HH + h);
    const float c = -logf(10000.0f) / (float)HH;
    float d0 = expf((float)h * c);
    float d1 = expf((float)(h + 2) * c);
    float a0 = (float)n * d0, a1 = (float)n * d1;
    e.x += sinf(a0); e.y += cosf(a0);
    e.z += sinf(a1); e.w += cosf(a1);
    *(float4*)(g_X + (size_t)bn * HH + h) = e;
}

// ---------------- 2) SGEMM: C[M,768] = A[M,768] @ W[768,768] + bias --------
__global__ __launch_bounds__(256, 2) void sgemm768(
    const float* __restrict__ A, const float* __restrict__ W,
    const float* __restrict__ bias, float* __restrict__ C, int M)
{
    __shared__ float As[8][128];
    __shared__ float Bs[8][128];
    const int tid = threadIdx.x;
    const int bm = blockIdx.y * 128, bn = blockIdx.x * 128;
    const int tx = tid & 15, ty = tid >> 4;
    const int arow = tid >> 1, acol = (tid & 1) * 4;
    const int brow = tid >> 5, bcol = (tid & 31) * 4;
    const bool aval = (bm + arow) < M;
    const float* Ap = A + (size_t)(bm + arow) * HH + acol;
    const float* Wp = W + (size_t)brow * HH + bn + bcol;

    float acc[8][8];
    #pragma unroll
    for (int i = 0; i < 8; i++)
        #pragma unroll
        for (int j = 0; j < 8; j++) acc[i][j] = 0.f;

    for (int k0 = 0; k0 < HH; k0 += 8) {
        float4 av = aval ? *(const float4*)(Ap + k0) : make_float4(0.f, 0.f, 0.f, 0.f);
        float4 bv = *(const float4*)(Wp + (size_t)k0 * HH);
        __syncthreads();
        As[acol + 0][arow] = av.x;
        As[acol + 1][arow] = av.y;
        As[acol + 2][arow] = av.z;
        As[acol + 3][arow] = av.w;
        *(float4*)&Bs[brow][bcol] = bv;
        __syncthreads();
        #pragma unroll
        for (int k = 0; k < 8; k++) {
            float ar[8], br[8];
            *(float4*)&ar[0] = *(const float4*)&As[k][ty * 8];
            *(float4*)&ar[4] = *(const float4*)&As[k][ty * 8 + 4];
            *(float4*)&br[0] = *(const float4*)&Bs[k][tx * 8];
            *(float4*)&br[4] = *(const float4*)&Bs[k][tx * 8 + 4];
            #pragma unroll
            for (int i = 0; i < 8; i++)
                #pragma unroll
                for (int j = 0; j < 8; j++)
                    acc[i][j] = fmaf(ar[i], br[j], acc[i][j]);
        }
    }

    float bb[8];
    *(float4*)&bb[0] = *(const float4*)(bias + bn + tx * 8);
    *(float4*)&bb[4] = *(const float4*)(bias + bn + tx * 8 + 4);
    #pragma unroll
    for (int i = 0; i < 8; i++) {
        int row = bm + ty * 8 + i;
        if (row < M) {
            float4 o0, o1;
            o0.x = acc[i][0] + bb[0]; o0.y = acc[i][1] + bb[1];
            o0.z = acc[i][2] + bb[2]; o0.w = acc[i][3] + bb[3];
            o1.x = acc[i][4] + bb[4]; o1.y = acc[i][5] + bb[5];
            o1.z = acc[i][6] + bb[6]; o1.w = acc[i][7] + bb[7];
            *(float4*)(C + (size_t)row * HH + bn + tx * 8) = o0;
            *(float4*)(C + (size_t)row * HH + bn + tx * 8 + 4) = o1;
        }
    }
}

// ---------------- 3) GAT attention: masked softmax of leaky_relu scores ----
__global__ void gat_att_kernel(const float* __restrict__ Wh,
                               const float* __restrict__ a,
                               const float* __restrict__ ab,
                               const int* __restrict__ adj,
                               float* __restrict__ att)
{
    int b = blockIdx.x;
    int t = threadIdx.x, lane = t & 31, w = t >> 5;   // 8 warps
    __shared__ float asrc[NN], adst[NN];
    const float* whb = Wh + (size_t)b * NN * HH;

    for (int n = w; n < NN; n += 8) {
        const float4* row = (const float4*)(whb + (size_t)n * HH);
        float s1 = 0.f, s2 = 0.f;
        for (int c2 = lane; c2 < HH / 4; c2 += 32) {
            float4 x = row[c2];
            float4 u = ((const float4*)a)[c2];
            float4 v = ((const float4*)a)[HH / 4 + c2];
            s1 += x.x * u.x + x.y * u.y + x.z * u.z + x.w * u.w;
            s2 += x.x * v.x + x.y * v.y + x.z * v.z + x.w * v.w;
        }
        #pragma unroll
        for (int o = 16; o; o >>= 1) {
            s1 += __shfl_xor_sync(~0u, s1, o);
            s2 += __shfl_xor_sync(~0u, s2, o);
        }
        if (lane == 0) { asrc[n] = s1; adst[n] = s2; }
    }
    __syncthreads();

    float abv = *ab;
    const int* adjb = adj + b * NN * NN;
    for (int i = w; i < NN; i += 8) {
        float ai = asrc[i];
        // lane covers j = lane and j2 = lane+32
        int j2 = lane + 32;
        float v0 = ai + adst[lane] + abv;
        v0 = v0 >= 0.f ? v0 : 0.3f * v0;
        float e0 = (adjb[i * NN + lane] > 0) ? v0 : -1e30f;
        float e1 = -1e30f;
        if (j2 < NN) {
            float v1 = ai + adst[j2] + abv;
            v1 = v1 >= 0.f ? v1 : 0.3f * v1;
            e1 = (adjb[i * NN + j2] > 0) ? v1 : -1e30f;
        }
        float m = fmaxf(e0, e1);
        #pragma unroll
        for (int o = 16; o; o >>= 1) m = fmaxf(m, __shfl_xor_sync(~0u, m, o));
        float x0 = expf(e0 - m);
        float x1 = (j2 < NN) ? expf(e1 - m) : 0.f;
        float s = x0 + x1;
        #pragma unroll
        for (int o = 16; o; o >>= 1) s += __shfl_xor_sync(~0u, s, o);
        float inv = 1.f / s;
        att[((size_t)b * NN + i) * NN + lane] = x0 * inv;
        if (j2 < NN) att[((size_t)b * NN + i) * NN + j2] = x1 * inv;
    }
}

// ---------------- 4) apply attention: out = elu(att @ Wh) (+ residual) -----
__global__ __launch_bounds__(256) void gat_apply_kernel(
    const float* __restrict__ att, const float* __restrict__ Wh,
    const float* __restrict__ resid, float* __restrict__ out)
{
    int b = blockIdx.y, ch = blockIdx.x;       // 6 chunks of 128 cols
    __shared__ float att_s[NN * NN];           // 10 KB
    __shared__ float whs[NN][128];             // 25.6 KB
    int t = threadIdx.x;
    for (int idx = t; idx < NN * NN; idx += 256)
        att_s[idx] = att[(size_t)b * NN * NN + idx];
    const float* whb = Wh + (size_t)b * NN * HH + ch * 128;
    for (int idx = t; idx < NN * 32; idx += 256) {
        int r = idx >> 5, c = (idx & 31) * 4;
        *(float4*)&whs[r][c] = *(const float4*)(whb + (size_t)r * HH + c);
    }
    __syncthreads();
    int hl = t & 127, i0 = t >> 7;
    for (int i = i0; i < NN; i += 2) {
        float acc = 0.f;
        #pragma unroll
        for (int j = 0; j < NN; j++)
            acc = fmaf(att_s[i * NN + j], whs[j][hl], acc);
        float val = acc > 0.f ? acc : expm1f(acc);
        size_t off = ((size_t)b * NN + i) * HH + ch * 128 + hl;
        if (resid) val += resid[off];
        out[off] = val;
    }
}

// ---------------- 5) attention pooling over N utterances -------------------
__global__ void pool_kernel(const float* __restrict__ T,
                            const float* __restrict__ v,
                            const float* __restrict__ Hres,
                            float* __restrict__ D)
{
    int b = blockIdx.x;
    int t = threadIdx.x, lane = t & 31, w = t >> 5;
    __shared__ float sc[NN];
    for (int n = w; n < NN; n += 8) {
        const float4* row = (const float4*)(T + ((size_t)b * NN + n) * HH);
        float s = 0.f;
        for (int c2 = lane; c2 < HH / 4; c2 += 32) {
            float4 x = row[c2];
            float4 u = ((const float4*)v)[c2];
            s += tanhf(x.x) * u.x + tanhf(x.y) * u.y +
                 tanhf(x.z) * u.z + tanhf(x.w) * u.w;
        }
        #pragma unroll
        for (int o = 16; o; o >>= 1) s += __shfl_xor_sync(~0u, s, o);
        if (lane == 0) sc[n] = s;
    }
    __syncthreads();
    if (t == 0) {
        float m = -1e30f;
        for (int n = 0; n < NN; n++) m = fmaxf(m, sc[n]);
        float s = 0.f;
        for (int n = 0; n < NN; n++) { sc[n] = expf(sc[n] - m); s += sc[n]; }
        float inv = 1.f / s;
        for (int n = 0; n < NN; n++) sc[n] *= inv;
    }
    __syncthreads();
    for (int h = t; h < HH; h += 256) {
        float acc = 0.f;
        #pragma unroll 5
        for (int n = 0; n < NN; n++)
            acc = fmaf(sc[n], Hres[((size_t)b * NN + n) * HH + h], acc);
        D[(size_t)b * HH + h] = acc;
    }
}

// ---------------- launch ----------------------------------------------------
extern "C" void kernel_launch(void* const* d_in, const int* in_sizes, int n_in,
                              void* d_out, int out_size)
{
    const float* emb = (const float*)d_in[0];
    const int*   ids = (const int*)  d_in[1];
    const int*   adj = (const int*)  d_in[2];
    const float* W1  = (const float*)d_in[3];
    const float* b1  = (const float*)d_in[4];
    const float* a1  = (const float*)d_in[5];
    const float* ab1 = (const float*)d_in[6];
    const float* W2  = (const float*)d_in[7];
    const float* b2  = (const float*)d_in[8];
    const float* a2  = (const float*)d_in[9];
    const float* ab2 = (const float*)d_in[10];
    const float* Wa  = (const float*)d_in[11];
    const float* ba  = (const float*)d_in[12];
    const float* v   = (const float*)d_in[13];
    const float* Wl  = (const float*)d_in[14];
    const float* bl  = (const float*)d_in[15];
    float* out = (float*)d_out;

    void *pX, *pWh, *pH1, *pHres, *pT, *pAtt, *pD;
    cudaGetSymbolAddress(&pX, g_X);
    cudaGetSymbolAddress(&pWh, g_Wh);
    cudaGetSymbolAddress(&pH1, g_H1);
    cudaGetSymbolAddress(&pHres, g_Hres);
    cudaGetSymbolAddress(&pT, g_T);
    cudaGetSymbolAddress(&pAtt, g_att);
    cudaGetSymbolAddress(&pD, g_D);
    float* X    = (float*)pX;
    float* Wh   = (float*)pWh;
    float* H1   = (float*)pH1;
    float* Hres = (float*)pHres;
    float* T    = (float*)pT;
    float* Att  = (float*)pAtt;
    float* D    = (float*)pD;

    dim3 ggemm(HH / 128, (MTOT + 127) / 128);   // (6, 25)
    dim3 gfin(HH / 128, 1);                     // final GEMM M=64
    dim3 gapply(HH / 128, BB);                  // (6, 64)

    // 1) gather + PE
    gather_pe_kernel<<<MTOT, HH / 4>>>(emb, ids);
    // 2) Wh1 = X @ W1 + b1
    sgemm768<<<ggemm, 256>>>(X, W1, b1, Wh, MTOT);
    // 3) GAT layer 1 attention + apply (elu)
    gat_att_kernel<<<BB, 256>>>(Wh, a1, ab1, adj, Att);
    gat_apply_kernel<<<gapply, 256>>>(Att, Wh, nullptr, H1);
    // 4) Wh2 = H1 @ W2 + b2
    sgemm768<<<ggemm, 256>>>(H1, W2, b2, Wh, MTOT);
    // 5) GAT layer 2 attention + apply (elu + residual X)
    gat_att_kernel<<<BB, 256>>>(Wh, a2, ab2, adj, Att);
    gat_apply_kernel<<<gapply, 256>>>(Att, Wh, X, Hres);
    // 6) T = Hres @ Wa + ba
    sgemm768<<<ggemm, 256>>>(Hres, Wa, ba, T, MTOT);
    // 7) attention pooling -> D[64,768]
    pool_kernel<<<BB, 256>>>(T, v, Hres, D);
    // 8) out = D @ Wl + bl
    sgemm768<<<gfin, 256>>>(D, Wl, bl, out, BB);
}